// round 3
// baseline (speedup 1.0000x reference)
#include <cuda_runtime.h>

// ----------------------------------------------------------------------------
// Problem constants
// ----------------------------------------------------------------------------
#define N_CHR 50000
#define E_CHR 500000
#define N_SLV 30000
#define E_SLV 300000
#define BATCH 256
#define FEAT  64
#define DIM   128
#define HALF  64
#define ENS   3
#define SLOT  ((long)N_CHR * DIM)   // per-ensemble scratch slot (floats)

// ----------------------------------------------------------------------------
// Device scratch (static globals; no allocation anywhere)
// ----------------------------------------------------------------------------
__device__ float g_ax[N_CHR * FEAT];        // aggregated input features (shared across ens)
__device__ float g_bufA[ENS * N_CHR * DIM]; // h0 / g2
__device__ float g_bufB[ENS * N_CHR * DIM]; // g1 / a2
__device__ float g_bufC[ENS * N_CHR * DIM]; // a1
__device__ float g_rep[ENS * BATCH * HALF]; // pooled representation
__device__ float g_hg[BATCH * 2 * ENS * DIM]; // concatenated head outputs [256,768]
__device__ float g_hg2[BATCH * DIM];        // fc1 output

// ----------------------------------------------------------------------------
// Vectorized scatter-add over edges: out[dst[e]][f..f+3] += in[src[e]][f..f+3]
// TPE = F/4 threads per edge; red.global.add.v4.f32 (REDG, no return).
// ----------------------------------------------------------------------------
template <int LOGTPE>
__global__ void scatter_vec_kernel(const float* __restrict__ in,
                                   float* __restrict__ out,
                                   const int* __restrict__ srci,
                                   const int* __restrict__ dsti,
                                   int E)
{
    const int TPE = 1 << LOGTPE;   // threads per edge
    const int F = TPE * 4;         // features per node
    long tid = (long)blockIdx.x * blockDim.x + threadIdx.x;
    int e = (int)(tid >> LOGTPE);
    if (e >= E) return;
    int f = ((int)tid & (TPE - 1)) << 2;
    float4 v = *(const float4*)(in + (long)srci[e] * F + f);
    float* p = out + (long)dsti[e] * F + f;
    asm volatile("red.global.add.v4.f32 [%0], {%1,%2,%3,%4};"
                 :: "l"(p), "f"(v.x), "f"(v.y), "f"(v.z), "f"(v.w)
                 : "memory");
}

// ----------------------------------------------------------------------------
// Global add pool with fused relu, vectorized + ensemble-fused (NZ=3):
//   rep[z][batch[n]][f..f+3] += relu(in[z][n][f..f+3])      (F = 64)
// ----------------------------------------------------------------------------
__global__ void pool_vec_kernel(const float* __restrict__ in,
                                const int* __restrict__ batchids,
                                float* __restrict__ out,
                                int N, long sIn, long sOut)
{
    long tid = (long)blockIdx.x * blockDim.x + threadIdx.x;
    int n = (int)(tid >> 4);       // 16 threads per node (64 feats / 4)
    if (n >= N) return;
    int f = ((int)tid & 15) << 2;
    int b = batchids[n];
    long so = (long)n * HALF + f;
    long doff = (long)b * HALF + f;
#pragma unroll
    for (int z = 0; z < ENS; z++) {
        float4 v = *(const float4*)(in + z * sIn + so);
        v.x = fmaxf(v.x, 0.0f); v.y = fmaxf(v.y, 0.0f);
        v.z = fmaxf(v.z, 0.0f); v.w = fmaxf(v.w, 0.0f);
        float* p = out + z * sOut + doff;
        asm volatile("red.global.add.v4.f32 [%0], {%1,%2,%3,%4};"
                     :: "l"(p), "f"(v.x), "f"(v.y), "f"(v.z), "f"(v.w)
                     : "memory");
    }
}

// ----------------------------------------------------------------------------
// Big fp32 GEMM for node matrices: C[nrows, BN] = op(A[nrows, K]) @ W[K, BN]
// BM=128, BK=8, 256 threads, 8x(BN/16) micro-tile. ldA = K, ldC = BN.
// Optionally zeroes a side buffer Z[nrows, ZW] (fused memset for the next
// scatter target). RELU_IN applies relu to A on load; RELU_OUT to C on store.
// ----------------------------------------------------------------------------
template <int BN, int ZW, int RELU_IN, int RELU_OUT>
__global__ __launch_bounds__(256)
void gemm_big(const float* __restrict__ A, const float* __restrict__ W,
              float* __restrict__ C, float* __restrict__ Z,
              int nrows, int K)
{
    const int BM = 128, BK = 8, TM = 8, TN = BN / 16;
    __shared__ float As[BK][132];   // stride 132: conflict-free transposed store
    __shared__ float Ws[BK][BN];

    int tid = threadIdx.x;
    int row0 = blockIdx.x * BM;

    // Fused zero of the side buffer (rows of this block)
    if (ZW > 0 && Z) {
        const int f4PerRow = ZW >> 2;
#pragma unroll 4
        for (int i = tid; i < BM * f4PerRow; i += 256) {
            int r = i / f4PerRow;
            int c = i - r * f4PerRow;
            int row = row0 + r;
            if (row < nrows)
                ((float4*)Z)[(long)row * f4PerRow + c] = make_float4(0.f, 0.f, 0.f, 0.f);
        }
    }

    int tx = tid & 15;
    int ty = tid >> 4;

    // A loader: one float4 per thread per tile
    int arow = tid >> 1;            // 0..127
    int akq = (tid & 1) * 4;        // 0 or 4
    // W loader
    int wk, wn4;
    if (BN == 128) { wk = tid >> 5; wn4 = (tid & 31) * 4; }
    else           { wk = tid >> 4; wn4 = (tid & 15) * 4; }

    float acc[TM][TN];
#pragma unroll
    for (int i = 0; i < TM; i++)
#pragma unroll
        for (int j = 0; j < TN; j++) acc[i][j] = 0.0f;

    for (int k0 = 0; k0 < K; k0 += BK) {
        // A tile -> transposed smem
        {
            int row = row0 + arow;
            float4 v = make_float4(0.f, 0.f, 0.f, 0.f);
            if (row < nrows)
                v = *(const float4*)(A + (long)row * K + k0 + akq);
            if (RELU_IN) {
                v.x = fmaxf(v.x, 0.f); v.y = fmaxf(v.y, 0.f);
                v.z = fmaxf(v.z, 0.f); v.w = fmaxf(v.w, 0.f);
            }
            As[akq + 0][arow] = v.x;
            As[akq + 1][arow] = v.y;
            As[akq + 2][arow] = v.z;
            As[akq + 3][arow] = v.w;
        }
        // W tile
        if (BN == 128 || tid < 128) {
            float4 v = *(const float4*)(W + (long)(k0 + wk) * BN + wn4);
            *(float4*)&Ws[wk][wn4] = v;
        }
        __syncthreads();

#pragma unroll
        for (int k = 0; k < BK; k++) {
            float ra[TM], rb[TN];
#pragma unroll
            for (int i = 0; i < TM; i++) ra[i] = As[k][ty + i * 16];
#pragma unroll
            for (int j = 0; j < TN; j++) rb[j] = Ws[k][tx + j * 16];
#pragma unroll
            for (int i = 0; i < TM; i++)
#pragma unroll
                for (int j = 0; j < TN; j++)
                    acc[i][j] = fmaf(ra[i], rb[j], acc[i][j]);
        }
        __syncthreads();
    }

#pragma unroll
    for (int i = 0; i < TM; i++) {
        int row = row0 + ty + i * 16;
        if (row < nrows) {
#pragma unroll
            for (int j = 0; j < TN; j++) {
                float v = acc[i][j];
                if (RELU_OUT) v = fmaxf(v, 0.f);
                C[(long)row * BN + tx + j * 16] = v;
            }
        }
    }
}

// ----------------------------------------------------------------------------
// Small register-tiled GEMM (heads / fc1): C = op(A) @ W (+bias), BN=128.
// blockIdx.z = ensemble with independent strides.
// ----------------------------------------------------------------------------
__global__ void gemm_small(const float* __restrict__ A,
                           const float* __restrict__ W,
                           const float* __restrict__ bias,
                           float* __restrict__ C,
                           int nrows, int K, int ldA, int ldC,
                           long sA, long sW, long sC, long sB)
{
    const int BM = 64, BK = 16, TM = 4, BN = 128, TN = 8;
    A += blockIdx.z * sA;
    W += blockIdx.z * sW;
    C += blockIdx.z * sC;
    if (bias) bias += blockIdx.z * sB;

    __shared__ float As[BK][BM + 1];
    __shared__ float Ws[BK][BN];

    int tid = threadIdx.x;
    int tx = tid & 15;
    int ty = tid >> 4;
    int row0 = blockIdx.x * BM;

    float acc[TM][TN];
#pragma unroll
    for (int i = 0; i < TM; i++)
#pragma unroll
        for (int j = 0; j < TN; j++) acc[i][j] = 0.0f;

    for (int k0 = 0; k0 < K; k0 += BK) {
#pragma unroll
        for (int i = 0; i < (BM * BK) / 256; i++) {
            int t = tid + i * 256;
            int m = t >> 4;
            int k = t & 15;
            int row = row0 + m;
            As[k][m] = (row < nrows) ? A[(long)row * ldA + k0 + k] : 0.0f;
        }
#pragma unroll
        for (int i = 0; i < (BN * BK) / 256; i++) {
            int t = tid + i * 256;
            int n = t & 127;
            int k = t >> 7;
            Ws[k][n] = W[(long)(k0 + k) * BN + n];
        }
        __syncthreads();

#pragma unroll
        for (int k = 0; k < BK; k++) {
            float ra[TM], rb[TN];
#pragma unroll
            for (int i = 0; i < TM; i++) ra[i] = As[k][ty + i * 16];
#pragma unroll
            for (int j = 0; j < TN; j++) rb[j] = Ws[k][tx + j * 16];
#pragma unroll
            for (int i = 0; i < TM; i++)
#pragma unroll
                for (int j = 0; j < TN; j++)
                    acc[i][j] = fmaf(ra[i], rb[j], acc[i][j]);
        }
        __syncthreads();
    }

#pragma unroll
    for (int i = 0; i < TM; i++) {
        int row = row0 + ty + i * 16;
        if (row < nrows) {
#pragma unroll
            for (int j = 0; j < TN; j++) {
                int col = tx + j * 16;
                float v = acc[i][j];
                if (bias) v += bias[col];
                v = fmaxf(v, 0.0f);   // all small GEMMs here are relu'd
                C[(long)row * ldC + col] = v;
            }
        }
    }
}

// ----------------------------------------------------------------------------
// Final fc2: out[row] = dot(hg2[row,:], W[:,0]) + b[0]   ([256,128]@[128,1])
// ----------------------------------------------------------------------------
__global__ void fc2_kernel(const float* __restrict__ A,
                           const float* __restrict__ W,
                           const float* __restrict__ b,
                           float* __restrict__ out)
{
    int row = blockIdx.x;
    float v = A[row * DIM + threadIdx.x] * W[threadIdx.x];
#pragma unroll
    for (int o = 16; o > 0; o >>= 1) v += __shfl_down_sync(0xffffffffu, v, o);
    __shared__ float s[4];
    if ((threadIdx.x & 31) == 0) s[threadIdx.x >> 5] = v;
    __syncthreads();
    if (threadIdx.x == 0) out[row] = s[0] + s[1] + s[2] + s[3] + b[0];
}

// ----------------------------------------------------------------------------
// Host-side orchestration
// ----------------------------------------------------------------------------
static void run_branch(const float* x, const int* ei, const int* batchids,
                       const float* W0, const float* W1, const float* W2,
                       const float* fcW, const float* fcb,
                       int N, int E, float* hg_base,
                       float* p_ax, float* p_bufA, float* p_bufB, float* p_bufC,
                       float* p_rep)
{
    const int* src = ei;
    const int* dst = ei + E;
    unsigned gemmBlocks = (unsigned)((N + 127) / 128);

    // Layer 0 aggregation: agg(x) once, shared by all ensembles (64-wide).
    cudaMemsetAsync(p_ax, 0, (size_t)N * FEAT * sizeof(float));
    {
        long total = (long)E * 16;
        scatter_vec_kernel<4><<<(unsigned)((total + 255) / 256), 256>>>(
            x, p_ax, src, dst, E);
    }

    // Per-ensemble pipeline, interleaved for L2 locality.
    for (int e = 0; e < ENS; e++) {
        float* h0 = p_bufA + e * SLOT;
        float* g1 = p_bufB + e * SLOT;
        float* a1 = p_bufC + e * SLOT;
        float* g2 = p_bufA + e * SLOT;   // reuses h0 slot (64-wide)
        float* a2 = p_bufB + e * SLOT;   // reuses g1 slot (64-wide)

        // h0 = relu(ax @ W0[e]); fused zero of a1 slot (128-wide)
        gemm_big<128, 128, 0, 1><<<gemmBlocks, 256>>>(
            p_ax, W0 + (long)e * FEAT * DIM, h0, a1, N, FEAT);
        // g1 = h0 @ W1[e]
        gemm_big<128, 0, 0, 0><<<gemmBlocks, 256>>>(
            h0, W1 + (long)e * DIM * DIM, g1, nullptr, N, DIM);
        // a1 += scatter(g1) over edges (128-wide)
        {
            long total = (long)E * 32;
            scatter_vec_kernel<5><<<(unsigned)((total + 255) / 256), 256>>>(
                g1, a1, src, dst, E);
        }
        // g2 = relu(a1) @ W2[e] (64-wide); fused zero of a2 slot (64-wide)
        gemm_big<64, 64, 1, 0><<<gemmBlocks, 256>>>(
            a1, W2 + (long)e * DIM * HALF, g2, a2, N, DIM);
        // a2 += scatter(g2) over edges (64-wide)
        {
            long total = (long)E * 16;
            scatter_vec_kernel<4><<<(unsigned)((total + 255) / 256), 256>>>(
                g2, a2, src, dst, E);
        }
    }

    // Pool: rep[e] = segment_sum(relu(a2[e]), batchids)   (a2 lives in bufB)
    cudaMemsetAsync(p_rep, 0, (size_t)ENS * BATCH * HALF * sizeof(float));
    {
        long total = (long)N * 16;
        pool_vec_kernel<<<(unsigned)((total + 255) / 256), 256>>>(
            p_bufB, batchids, p_rep, N, SLOT, (long)BATCH * HALF);
    }

    // Heads: hg[:, off + e*128 ...] = relu(rep[e] @ fcW[e] + fcb[e])
    {
        dim3 g((BATCH + 63) / 64, 1, ENS);
        gemm_small<<<g, 256>>>(p_rep, fcW, fcb, hg_base, BATCH, HALF, HALF,
                               2 * ENS * DIM,
                               (long)BATCH * HALF, (long)HALF * DIM, DIM, DIM);
    }
}

extern "C" void kernel_launch(void* const* d_in, const int* in_sizes, int n_in,
                              void* d_out, int out_size)
{
    // Resolve input ordering at runtime (dict order vs signature order).
    int i_chr_x, i_slv_x, i_chr_ei, i_slv_ei, i_chr_b, i_slv_b;
    int i_cW0, i_cW1, i_cW2, i_sW0, i_sW1, i_sW2;
    int i_cfcW, i_cfcB, i_sfcW, i_sfcB, i_fc1W, i_fc1B, i_fc2W, i_fc2B;
    if (in_sizes[2] == 2 * E_CHR) {
        i_chr_x = 0;  i_slv_x = 1;  i_chr_ei = 2; i_slv_ei = 3;
        i_chr_b = 4;  i_slv_b = 5;
        i_cW0 = 6;  i_cW1 = 7;  i_cW2 = 8;
        i_sW0 = 9;  i_sW1 = 10; i_sW2 = 11;
        i_cfcW = 12; i_cfcB = 13; i_sfcW = 14; i_sfcB = 15;
        i_fc1W = 16; i_fc1B = 17; i_fc2W = 18; i_fc2B = 19;
    } else {
        i_chr_x = 0;  i_slv_x = 1;
        i_cW0 = 2;  i_cW1 = 3;  i_cW2 = 4;
        i_sW0 = 5;  i_sW1 = 6;  i_sW2 = 7;
        i_cfcW = 8;  i_cfcB = 9;  i_sfcW = 10; i_sfcB = 11;
        i_fc1W = 12; i_fc1B = 13; i_fc2W = 14; i_fc2B = 15;
        i_chr_ei = 16; i_slv_ei = 17; i_chr_b = 18; i_slv_b = 19;
    }

    const float* chr_x = (const float*)d_in[i_chr_x];
    const float* slv_x = (const float*)d_in[i_slv_x];
    const int* chr_ei = (const int*)d_in[i_chr_ei];
    const int* slv_ei = (const int*)d_in[i_slv_ei];
    const int* chr_bi = (const int*)d_in[i_chr_b];
    const int* slv_bi = (const int*)d_in[i_slv_b];
    const float* cW0 = (const float*)d_in[i_cW0];
    const float* cW1 = (const float*)d_in[i_cW1];
    const float* cW2 = (const float*)d_in[i_cW2];
    const float* sW0 = (const float*)d_in[i_sW0];
    const float* sW1 = (const float*)d_in[i_sW1];
    const float* sW2 = (const float*)d_in[i_sW2];
    const float* cfcW = (const float*)d_in[i_cfcW];
    const float* cfcB = (const float*)d_in[i_cfcB];
    const float* sfcW = (const float*)d_in[i_sfcW];
    const float* sfcB = (const float*)d_in[i_sfcB];
    const float* fc1W = (const float*)d_in[i_fc1W];
    const float* fc1B = (const float*)d_in[i_fc1B];
    const float* fc2W = (const float*)d_in[i_fc2W];
    const float* fc2B = (const float*)d_in[i_fc2B];

    float *p_ax, *p_bufA, *p_bufB, *p_bufC, *p_rep, *p_hg, *p_hg2;
    cudaGetSymbolAddress((void**)&p_ax,   g_ax);
    cudaGetSymbolAddress((void**)&p_bufA, g_bufA);
    cudaGetSymbolAddress((void**)&p_bufB, g_bufB);
    cudaGetSymbolAddress((void**)&p_bufC, g_bufC);
    cudaGetSymbolAddress((void**)&p_rep,  g_rep);
    cudaGetSymbolAddress((void**)&p_hg,   g_hg);
    cudaGetSymbolAddress((void**)&p_hg2,  g_hg2);

    // chr branch -> hg columns [0, 384)
    run_branch(chr_x, chr_ei, chr_bi, cW0, cW1, cW2, cfcW, cfcB,
               N_CHR, E_CHR, p_hg, p_ax, p_bufA, p_bufB, p_bufC, p_rep);
    // slv branch -> hg columns [384, 768)
    run_branch(slv_x, slv_ei, slv_bi, sW0, sW1, sW2, sfcW, sfcB,
               N_SLV, E_SLV, p_hg + ENS * DIM, p_ax, p_bufA, p_bufB, p_bufC, p_rep);

    // fc1: hg2 = relu(hg @ fc1W + fc1B)   [256,768]@[768,128]
    {
        dim3 g((BATCH + 63) / 64, 1, 1);
        gemm_small<<<g, 256>>>(p_hg, fc1W, fc1B, p_hg2, BATCH, 2 * ENS * DIM,
                               2 * ENS * DIM, DIM, 0, 0, 0, 0);
    }

    // fc2: out = hg2 @ fc2W + fc2B   [256,128]@[128,1]
    fc2_kernel<<<BATCH, DIM>>>(p_hg2, fc2W, fc2B, (float*)d_out);
}

// round 5
// speedup vs baseline: 1.1875x; 1.1875x over previous
#include <cuda_runtime.h>

// ----------------------------------------------------------------------------
// Problem constants
// ----------------------------------------------------------------------------
#define N_CHR 50000
#define E_CHR 500000
#define N_SLV 30000
#define E_SLV 300000
#define BATCH 256
#define FEAT  64
#define DIM   128
#define HALF  64
#define ENS   3
#define SLOT  ((long)N_CHR * DIM)   // per-ensemble scratch slot (floats)

// ----------------------------------------------------------------------------
// Device scratch (static globals; no allocation anywhere)
// ----------------------------------------------------------------------------
__device__ float g_ax[N_CHR * FEAT];          // aggregated input features
__device__ float g_bufA[ENS * N_CHR * DIM];   // h0 / g2
__device__ float g_bufB[ENS * N_CHR * DIM];   // g1 / a2
__device__ float g_bufC[ENS * N_CHR * DIM];   // a1
__device__ float g_rep[ENS * BATCH * HALF];   // pooled representation
__device__ float g_hg[BATCH * 2 * ENS * DIM]; // concatenated head outputs [256,768]
__device__ float g_hg2[BATCH * DIM];          // fc1 output

// ----------------------------------------------------------------------------
// Vectorized fused-ensemble scatter-add over edges (round-2 proven config):
//   for z in [0,NZ): out[z][dst[e]][f..f+3] += in[z][src[e]][f..f+3]
// TPE = F/4 threads per edge; red.global.add.v4.f32 (REDG, no return).
// ----------------------------------------------------------------------------
template <int LOGTPE, int NZ>
__global__ void scatter_vec_kernel(const float* __restrict__ in,
                                   float* __restrict__ out,
                                   const int* __restrict__ srci,
                                   const int* __restrict__ dsti,
                                   int E, long sIn, long sOut)
{
    const int TPE = 1 << LOGTPE;   // threads per edge
    const int F = TPE * 4;         // features per node
    long tid = (long)blockIdx.x * blockDim.x + threadIdx.x;
    int e = (int)(tid >> LOGTPE);
    if (e >= E) return;
    int f = ((int)tid & (TPE - 1)) << 2;
    long so = (long)srci[e] * F + f;
    long doff = (long)dsti[e] * F + f;
#pragma unroll
    for (int z = 0; z < NZ; z++) {
        float4 v = *(const float4*)(in + z * sIn + so);
        float* p = out + z * sOut + doff;
        asm volatile("red.global.add.v4.f32 [%0], {%1,%2,%3,%4};"
                     :: "l"(p), "f"(v.x), "f"(v.y), "f"(v.z), "f"(v.w)
                     : "memory");
    }
}

// ----------------------------------------------------------------------------
// Global add pool with fused relu, vectorized + ensemble-fused (NZ=3):
//   rep[z][batch[n]][f..f+3] += relu(in[z][n][f..f+3])      (F = 64)
// ----------------------------------------------------------------------------
__global__ void pool_vec_kernel(const float* __restrict__ in,
                                const int* __restrict__ batchids,
                                float* __restrict__ out,
                                int N, long sIn, long sOut)
{
    long tid = (long)blockIdx.x * blockDim.x + threadIdx.x;
    int n = (int)(tid >> 4);       // 16 threads per node (64 feats / 4)
    if (n >= N) return;
    int f = ((int)tid & 15) << 2;
    int b = batchids[n];
    long so = (long)n * HALF + f;
    long doff = (long)b * HALF + f;
#pragma unroll
    for (int z = 0; z < ENS; z++) {
        float4 v = *(const float4*)(in + z * sIn + so);
        v.x = fmaxf(v.x, 0.0f); v.y = fmaxf(v.y, 0.0f);
        v.z = fmaxf(v.z, 0.0f); v.w = fmaxf(v.w, 0.0f);
        float* p = out + z * sOut + doff;
        asm volatile("red.global.add.v4.f32 [%0], {%1,%2,%3,%4};"
                     :: "l"(p), "f"(v.x), "f"(v.y), "f"(v.z), "f"(v.w)
                     : "memory");
    }
}

// ----------------------------------------------------------------------------
// FFMA2 (packed f32x2) GEMM:  C[nrows, BN] = op(A[nrows, K]) @ W[K, BN]
// BM=128, BK=8, 256 threads. Each thread owns 4 ROW-PAIRS x TN columns:
//   rows  = ty*2 + i*32 + {0,1}   (pair -> one 64-bit LDS + one fma.rn.f32x2)
//   cols  = tx + j*16
// Inner product: 32 FFMA2 per k instead of 64 FFMA -> 2x fp32 throughput
// (exact fp32 math, no precision change). blockIdx.z = ensemble with strides.
// ----------------------------------------------------------------------------
template <int BN, int RELU_IN, int RELU_OUT>
__global__ __launch_bounds__(256)
void gemm_f2(const float* __restrict__ A, const float* __restrict__ W,
             float* __restrict__ C, int nrows, int K,
             long sA, long sW, long sC)
{
    const int BM = 128, BK = 8, TN = BN / 16;
    A += blockIdx.z * sA;
    W += blockIdx.z * sW;
    C += blockIdx.z * sC;

    __shared__ __align__(16) float As[BK][132];  // transposed, 8B-friendly stride
    __shared__ __align__(16) float Ws[BK][BN];

    int tid = threadIdx.x;
    int tx = tid & 15;
    int ty = tid >> 4;
    int row0 = blockIdx.x * BM;

    // Loaders
    int arow = tid >> 1;            // 0..127
    int akq = (tid & 1) * 4;        // 0 or 4
    int wk, wn4;
    if (BN == 128) { wk = tid >> 5; wn4 = (tid & 31) * 4; }
    else           { wk = tid >> 4; wn4 = (tid & 15) * 4; }

    unsigned long long acc2[4][TN];
#pragma unroll
    for (int i = 0; i < 4; i++)
#pragma unroll
        for (int j = 0; j < TN; j++) acc2[i][j] = 0ull;

    for (int k0 = 0; k0 < K; k0 += BK) {
        // A tile -> transposed smem
        {
            int row = row0 + arow;
            float4 v = make_float4(0.f, 0.f, 0.f, 0.f);
            if (row < nrows)
                v = *(const float4*)(A + (long)row * K + k0 + akq);
            if (RELU_IN) {
                v.x = fmaxf(v.x, 0.f); v.y = fmaxf(v.y, 0.f);
                v.z = fmaxf(v.z, 0.f); v.w = fmaxf(v.w, 0.f);
            }
            As[akq + 0][arow] = v.x;
            As[akq + 1][arow] = v.y;
            As[akq + 2][arow] = v.z;
            As[akq + 3][arow] = v.w;
        }
        // W tile
        if (BN == 128 || tid < 128) {
            float4 v = *(const float4*)(W + (long)(k0 + wk) * BN + wn4);
            *(float4*)&Ws[wk][wn4] = v;
        }
        __syncthreads();

#pragma unroll
        for (int k = 0; k < BK; k++) {
            unsigned long long rav[4], rbv[TN];
#pragma unroll
            for (int i = 0; i < 4; i++) {
                float2 t = *(const float2*)&As[k][ty * 2 + i * 32];
                asm("mov.b64 %0, {%1, %2};" : "=l"(rav[i]) : "f"(t.x), "f"(t.y));
            }
#pragma unroll
            for (int j = 0; j < TN; j++) {
                float b = Ws[k][tx + j * 16];
                asm("mov.b64 %0, {%1, %1};" : "=l"(rbv[j]) : "f"(b));
            }
#pragma unroll
            for (int i = 0; i < 4; i++)
#pragma unroll
                for (int j = 0; j < TN; j++)
                    asm("fma.rn.f32x2 %0, %1, %2, %0;"
                        : "+l"(acc2[i][j]) : "l"(rav[i]), "l"(rbv[j]));
        }
        __syncthreads();
    }

    // Epilogue: unpack pairs, optional relu, store
#pragma unroll
    for (int i = 0; i < 4; i++) {
        int r0 = row0 + ty * 2 + i * 32;
#pragma unroll
        for (int j = 0; j < TN; j++) {
            float v0, v1;
            asm("mov.b64 {%0, %1}, %2;" : "=f"(v0), "=f"(v1) : "l"(acc2[i][j]));
            if (RELU_OUT) { v0 = fmaxf(v0, 0.f); v1 = fmaxf(v1, 0.f); }
            int col = tx + j * 16;
            if (r0 < nrows)     C[(long)r0 * BN + col] = v0;
            if (r0 + 1 < nrows) C[(long)(r0 + 1) * BN + col] = v1;
        }
    }
}

// ----------------------------------------------------------------------------
// Small register-tiled GEMM (heads / fc1): C = relu(A @ W + bias), BN=128.
// blockIdx.z = ensemble with independent strides.
// ----------------------------------------------------------------------------
__global__ void gemm_small(const float* __restrict__ A,
                           const float* __restrict__ W,
                           const float* __restrict__ bias,
                           float* __restrict__ C,
                           int nrows, int K, int ldA, int ldC,
                           long sA, long sW, long sC, long sB)
{
    const int BM = 64, BK = 16, TM = 4, BN = 128, TN = 8;
    A += blockIdx.z * sA;
    W += blockIdx.z * sW;
    C += blockIdx.z * sC;
    if (bias) bias += blockIdx.z * sB;

    __shared__ float As[BK][BM + 1];
    __shared__ float Ws[BK][BN];

    int tid = threadIdx.x;
    int tx = tid & 15;
    int ty = tid >> 4;
    int row0 = blockIdx.x * BM;

    float acc[TM][TN];
#pragma unroll
    for (int i = 0; i < TM; i++)
#pragma unroll
        for (int j = 0; j < TN; j++) acc[i][j] = 0.0f;

    for (int k0 = 0; k0 < K; k0 += BK) {
#pragma unroll
        for (int i = 0; i < (BM * BK) / 256; i++) {
            int t = tid + i * 256;
            int m = t >> 4;
            int k = t & 15;
            int row = row0 + m;
            As[k][m] = (row < nrows) ? A[(long)row * ldA + k0 + k] : 0.0f;
        }
#pragma unroll
        for (int i = 0; i < (BN * BK) / 256; i++) {
            int t = tid + i * 256;
            int n = t & 127;
            int k = t >> 7;
            Ws[k][n] = W[(long)(k0 + k) * BN + n];
        }
        __syncthreads();

#pragma unroll
        for (int k = 0; k < BK; k++) {
            float ra[TM], rb[TN];
#pragma unroll
            for (int i = 0; i < TM; i++) ra[i] = As[k][ty + i * 16];
#pragma unroll
            for (int j = 0; j < TN; j++) rb[j] = Ws[k][tx + j * 16];
#pragma unroll
            for (int i = 0; i < TM; i++)
#pragma unroll
                for (int j = 0; j < TN; j++)
                    acc[i][j] = fmaf(ra[i], rb[j], acc[i][j]);
        }
        __syncthreads();
    }

#pragma unroll
    for (int i = 0; i < TM; i++) {
        int row = row0 + ty + i * 16;
        if (row < nrows) {
#pragma unroll
            for (int j = 0; j < TN; j++) {
                int col = tx + j * 16;
                float v = acc[i][j];
                if (bias) v += bias[col];
                v = fmaxf(v, 0.0f);   // all small GEMMs here are relu'd
                C[(long)row * ldC + col] = v;
            }
        }
    }
}

// ----------------------------------------------------------------------------
// Final fc2: out[row] = dot(hg2[row,:], W[:,0]) + b[0]   ([256,128]@[128,1])
// ----------------------------------------------------------------------------
__global__ void fc2_kernel(const float* __restrict__ A,
                           const float* __restrict__ W,
                           const float* __restrict__ b,
                           float* __restrict__ out)
{
    int row = blockIdx.x;
    float v = A[row * DIM + threadIdx.x] * W[threadIdx.x];
#pragma unroll
    for (int o = 16; o > 0; o >>= 1) v += __shfl_down_sync(0xffffffffu, v, o);
    __shared__ float s[4];
    if ((threadIdx.x & 31) == 0) s[threadIdx.x >> 5] = v;
    __syncthreads();
    if (threadIdx.x == 0) out[row] = s[0] + s[1] + s[2] + s[3] + b[0];
}

// ----------------------------------------------------------------------------
// Host-side orchestration (round-2 structure: z-batched GEMMs, fused scatters)
// ----------------------------------------------------------------------------
static void run_branch(const float* x, const int* ei, const int* batchids,
                       const float* W0, const float* W1, const float* W2,
                       const float* fcW, const float* fcb,
                       int N, int E, float* hg_base,
                       float* p_ax, float* p_bufA, float* p_bufB, float* p_bufC,
                       float* p_rep)
{
    const int* src = ei;
    const int* dst = ei + E;
    unsigned gb = (unsigned)((N + 127) / 128);

    // Layer 0 aggregation: agg(x) once, shared by all ensembles (64-wide).
    cudaMemsetAsync(p_ax, 0, (size_t)N * FEAT * sizeof(float));
    {
        long total = (long)E * 16;
        scatter_vec_kernel<4, 1><<<(unsigned)((total + 255) / 256), 256>>>(
            x, p_ax, src, dst, E, 0, 0);
    }

    // h0[e] = relu(ax @ W0[e])   (z-batched, A shared: sA=0)
    gemm_f2<128, 0, 1><<<dim3(gb, 1, ENS), 256>>>(
        p_ax, W0, p_bufA, N, FEAT, 0, (long)FEAT * DIM, SLOT);

    // g1[e] = h0[e] @ W1[e]
    gemm_f2<128, 0, 0><<<dim3(gb, 1, ENS), 256>>>(
        p_bufA, W1, p_bufB, N, DIM, SLOT, (long)DIM * DIM, SLOT);

    // a1[e] = agg(g1[e])   (128-wide, fused over ensembles)
    for (int e = 0; e < ENS; e++)
        cudaMemsetAsync(p_bufC + e * SLOT, 0, (size_t)N * DIM * sizeof(float));
    {
        long total = (long)E * 32;
        scatter_vec_kernel<5, ENS><<<(unsigned)((total + 255) / 256), 256>>>(
            p_bufB, p_bufC, src, dst, E, SLOT, SLOT);
    }

    // g2[e] = relu(a1[e]) @ W2[e]   (64-wide output)
    gemm_f2<64, 1, 0><<<dim3(gb, 1, ENS), 256>>>(
        p_bufC, W2, p_bufA, N, DIM, SLOT, (long)DIM * HALF, SLOT);

    // a2[e] = agg(g2[e])   (64-wide, fused over ensembles)
    for (int e = 0; e < ENS; e++)
        cudaMemsetAsync(p_bufB + e * SLOT, 0, (size_t)N * HALF * sizeof(float));
    {
        long total = (long)E * 16;
        scatter_vec_kernel<4, ENS><<<(unsigned)((total + 255) / 256), 256>>>(
            p_bufA, p_bufB, src, dst, E, SLOT, SLOT);
    }

    // Pool: rep[e] = segment_sum(relu(a2[e]), batchids)
    cudaMemsetAsync(p_rep, 0, (size_t)ENS * BATCH * HALF * sizeof(float));
    {
        long total = (long)N * 16;
        pool_vec_kernel<<<(unsigned)((total + 255) / 256), 256>>>(
            p_bufB, batchids, p_rep, N, SLOT, (long)BATCH * HALF);
    }

    // Heads: hg[:, off + e*128 ...] = relu(rep[e] @ fcW[e] + fcb[e])
    {
        dim3 g((BATCH + 63) / 64, 1, ENS);
        gemm_small<<<g, 256>>>(p_rep, fcW, fcb, hg_base, BATCH, HALF, HALF,
                               2 * ENS * DIM,
                               (long)BATCH * HALF, (long)HALF * DIM, DIM, DIM);
    }
}

extern "C" void kernel_launch(void* const* d_in, const int* in_sizes, int n_in,
                              void* d_out, int out_size)
{
    // Resolve input ordering at runtime (dict order vs signature order).
    int i_chr_x, i_slv_x, i_chr_ei, i_slv_ei, i_chr_b, i_slv_b;
    int i_cW0, i_cW1, i_cW2, i_sW0, i_sW1, i_sW2;
    int i_cfcW, i_cfcB, i_sfcW, i_sfcB, i_fc1W, i_fc1B, i_fc2W, i_fc2B;
    if (in_sizes[2] == 2 * E_CHR) {
        i_chr_x = 0;  i_slv_x = 1;  i_chr_ei = 2; i_slv_ei = 3;
        i_chr_b = 4;  i_slv_b = 5;
        i_cW0 = 6;  i_cW1 = 7;  i_cW2 = 8;
        i_sW0 = 9;  i_sW1 = 10; i_sW2 = 11;
        i_cfcW = 12; i_cfcB = 13; i_sfcW = 14; i_sfcB = 15;
        i_fc1W = 16; i_fc1B = 17; i_fc2W = 18; i_fc2B = 19;
    } else {
        i_chr_x = 0;  i_slv_x = 1;
        i_cW0 = 2;  i_cW1 = 3;  i_cW2 = 4;
        i_sW0 = 5;  i_sW1 = 6;  i_sW2 = 7;
        i_cfcW = 8;  i_cfcB = 9;  i_sfcW = 10; i_sfcB = 11;
        i_fc1W = 12; i_fc1B = 13; i_fc2W = 14; i_fc2B = 15;
        i_chr_ei = 16; i_slv_ei = 17; i_chr_b = 18; i_slv_b = 19;
    }

    const float* chr_x = (const float*)d_in[i_chr_x];
    const float* slv_x = (const float*)d_in[i_slv_x];
    const int* chr_ei = (const int*)d_in[i_chr_ei];
    const int* slv_ei = (const int*)d_in[i_slv_ei];
    const int* chr_bi = (const int*)d_in[i_chr_b];
    const int* slv_bi = (const int*)d_in[i_slv_b];
    const float* cW0 = (const float*)d_in[i_cW0];
    const float* cW1 = (const float*)d_in[i_cW1];
    const float* cW2 = (const float*)d_in[i_cW2];
    const float* sW0 = (const float*)d_in[i_sW0];
    const float* sW1 = (const float*)d_in[i_sW1];
    const float* sW2 = (const float*)d_in[i_sW2];
    const float* cfcW = (const float*)d_in[i_cfcW];
    const float* cfcB = (const float*)d_in[i_cfcB];
    const float* sfcW = (const float*)d_in[i_sfcW];
    const float* sfcB = (const float*)d_in[i_sfcB];
    const float* fc1W = (const float*)d_in[i_fc1W];
    const float* fc1B = (const float*)d_in[i_fc1B];
    const float* fc2W = (const float*)d_in[i_fc2W];
    const float* fc2B = (const float*)d_in[i_fc2B];

    float *p_ax, *p_bufA, *p_bufB, *p_bufC, *p_rep, *p_hg, *p_hg2;
    cudaGetSymbolAddress((void**)&p_ax,   g_ax);
    cudaGetSymbolAddress((void**)&p_bufA, g_bufA);
    cudaGetSymbolAddress((void**)&p_bufB, g_bufB);
    cudaGetSymbolAddress((void**)&p_bufC, g_bufC);
    cudaGetSymbolAddress((void**)&p_rep,  g_rep);
    cudaGetSymbolAddress((void**)&p_hg,   g_hg);
    cudaGetSymbolAddress((void**)&p_hg2,  g_hg2);

    // chr branch -> hg columns [0, 384)
    run_branch(chr_x, chr_ei, chr_bi, cW0, cW1, cW2, cfcW, cfcB,
               N_CHR, E_CHR, p_hg, p_ax, p_bufA, p_bufB, p_bufC, p_rep);
    // slv branch -> hg columns [384, 768)
    run_branch(slv_x, slv_ei, slv_bi, sW0, sW1, sW2, sfcW, sfcB,
               N_SLV, E_SLV, p_hg + ENS * DIM, p_ax, p_bufA, p_bufB, p_bufC, p_rep);

    // fc1: hg2 = relu(hg @ fc1W + fc1B)   [256,768]@[768,128]
    {
        dim3 g((BATCH + 63) / 64, 1, 1);
        gemm_small<<<g, 256>>>(p_hg, fc1W, fc1B, p_hg2, BATCH, 2 * ENS * DIM,
                               2 * ENS * DIM, DIM, 0, 0, 0, 0);
    }

    // fc2: out = hg2 @ fc2W + fc2B   [256,128]@[128,1]
    fc2_kernel<<<BATCH, DIM>>>(p_hg2, fc2W, fc2B, (float*)d_out);
}

// round 6
// speedup vs baseline: 1.4624x; 1.2315x over previous
#include <cuda_runtime.h>

// ----------------------------------------------------------------------------
// Problem constants
// ----------------------------------------------------------------------------
#define N_CHR 50000
#define E_CHR 500000
#define N_SLV 30000
#define E_SLV 300000
#define BATCH 256
#define FEAT  64
#define DIM   128
#define HALF  64
#define ENS   3
#define SLOT  ((long)N_CHR * DIM)   // per-ensemble scratch slot (floats)

// ----------------------------------------------------------------------------
// Device scratch (static globals; no allocation anywhere)
// ----------------------------------------------------------------------------
__device__ float g_ax[N_CHR * FEAT];          // aggregated input features
__device__ float g_bufA[ENS * N_CHR * DIM];   // h0 / g2
__device__ float g_bufB[ENS * N_CHR * DIM];   // g1 / a2
__device__ float g_bufC[ENS * N_CHR * DIM];   // a1
__device__ float g_rep[ENS * BATCH * HALF];   // pooled representation
__device__ float g_hg[BATCH * 2 * ENS * DIM]; // concatenated head outputs [256,768]
__device__ float g_hg2[BATCH * DIM];          // fc1 output
// CSR scratch (sized for the larger graph; reused by slv after chr)
__device__ int g_cnt[N_CHR];                  // per-dst degree
__device__ int g_rowptr[N_CHR + 1];           // CSR row pointers
__device__ int g_pos[N_CHR];                  // atomic cursors for permute
__device__ int g_ssrc[E_CHR];                 // src indices sorted by dst

// ----------------------------------------------------------------------------
// CSR build: histogram -> prefix scan -> permute
// ----------------------------------------------------------------------------
__global__ void hist_kernel(const int* __restrict__ dsti, int* __restrict__ cnt,
                            int E)
{
    int e = blockIdx.x * blockDim.x + threadIdx.x;
    if (e < E) atomicAdd(&cnt[dsti[e]], 1);
}

// Single-block exclusive scan (warp-shuffle based), also fills pos = rowptr.
__global__ void scan_kernel(const int* __restrict__ cnt,
                            int* __restrict__ rowptr,
                            int* __restrict__ pos, int N, int E)
{
    __shared__ int warpTot[32];
    __shared__ int carry;
    int tid = threadIdx.x;
    int lane = tid & 31;
    int wid = tid >> 5;
    if (tid == 0) carry = 0;
    __syncthreads();

    for (int base = 0; base < N; base += 1024) {
        int i = base + tid;
        int v = (i < N) ? cnt[i] : 0;
        // warp inclusive scan
        int s = v;
#pragma unroll
        for (int off = 1; off < 32; off <<= 1) {
            int t = __shfl_up_sync(0xffffffffu, s, off);
            if (lane >= off) s += t;
        }
        if (lane == 31) warpTot[wid] = s;
        __syncthreads();
        if (wid == 0) {
            int w = warpTot[lane];
#pragma unroll
            for (int off = 1; off < 32; off <<= 1) {
                int t = __shfl_up_sync(0xffffffffu, w, off);
                if (lane >= off) w += t;
            }
            warpTot[lane] = w;
        }
        __syncthreads();
        int warpOff = (wid == 0) ? 0 : warpTot[wid - 1];
        int excl = carry + warpOff + s - v;
        if (i < N) { rowptr[i] = excl; pos[i] = excl; }
        __syncthreads();
        if (tid == 0) carry += warpTot[31];
        __syncthreads();
    }
    if (tid == 0) rowptr[N] = E;
}

__global__ void permute_kernel(const int* __restrict__ srci,
                               const int* __restrict__ dsti,
                               int* __restrict__ pos,
                               int* __restrict__ ssrc, int E)
{
    int e = blockIdx.x * blockDim.x + threadIdx.x;
    if (e < E) {
        int p = atomicAdd(&pos[dsti[e]], 1);
        ssrc[p] = srci[e];
    }
}

// ----------------------------------------------------------------------------
// CSR gather-aggregate: out[z][n][f..f+3] = sum over in-edges of in[z][src][f..f+3]
// TPE = F/4 threads per node; register accumulation, one streaming store.
// Replaces memset + scatter-REDG: cuts write traffic E*F -> N*F.
// ----------------------------------------------------------------------------
template <int LOGTPE, int NZ>
__global__ void gather_csr_kernel(const float* __restrict__ in,
                                  float* __restrict__ out,
                                  const int* __restrict__ rowptr,
                                  const int* __restrict__ ssrc,
                                  int N, long sIn, long sOut)
{
    const int TPE = 1 << LOGTPE;
    const int F = TPE * 4;
    long tid = (long)blockIdx.x * blockDim.x + threadIdx.x;
    int n = (int)(tid >> LOGTPE);
    if (n >= N) return;
    int f = ((int)tid & (TPE - 1)) << 2;
    int beg = rowptr[n];
    int end = rowptr[n + 1];

    float4 acc[NZ];
#pragma unroll
    for (int z = 0; z < NZ; z++) acc[z] = make_float4(0.f, 0.f, 0.f, 0.f);

    for (int i = beg; i < end; i++) {
        long so = (long)ssrc[i] * F + f;
#pragma unroll
        for (int z = 0; z < NZ; z++) {
            float4 v = *(const float4*)(in + z * sIn + so);
            acc[z].x += v.x; acc[z].y += v.y;
            acc[z].z += v.z; acc[z].w += v.w;
        }
    }
    long doff = (long)n * F + f;
#pragma unroll
    for (int z = 0; z < NZ; z++)
        *(float4*)(out + z * sOut + doff) = acc[z];
}

// ----------------------------------------------------------------------------
// Global add pool with fused relu, vectorized + ensemble-fused (NZ=3):
//   rep[z][batch[n]][f..f+3] += relu(in[z][n][f..f+3])      (F = 64)
// ----------------------------------------------------------------------------
__global__ void pool_vec_kernel(const float* __restrict__ in,
                                const int* __restrict__ batchids,
                                float* __restrict__ out,
                                int N, long sIn, long sOut)
{
    long tid = (long)blockIdx.x * blockDim.x + threadIdx.x;
    int n = (int)(tid >> 4);       // 16 threads per node (64 feats / 4)
    if (n >= N) return;
    int f = ((int)tid & 15) << 2;
    int b = batchids[n];
    long so = (long)n * HALF + f;
    long doff = (long)b * HALF + f;
#pragma unroll
    for (int z = 0; z < ENS; z++) {
        float4 v = *(const float4*)(in + z * sIn + so);
        v.x = fmaxf(v.x, 0.0f); v.y = fmaxf(v.y, 0.0f);
        v.z = fmaxf(v.z, 0.0f); v.w = fmaxf(v.w, 0.0f);
        float* p = out + z * sOut + doff;
        asm volatile("red.global.add.v4.f32 [%0], {%1,%2,%3,%4};"
                     :: "l"(p), "f"(v.x), "f"(v.y), "f"(v.z), "f"(v.w)
                     : "memory");
    }
}

// ----------------------------------------------------------------------------
// FFMA2 (packed f32x2) GEMM:  C[nrows, BN] = op(A[nrows, K]) @ W[K, BN]
// BM=128, BK=8, 256 threads, 4 row-pairs x TN cols per thread (fma.rn.f32x2).
// Exact fp32 math at 2x FFMA throughput. blockIdx.z = ensemble with strides.
// ----------------------------------------------------------------------------
template <int BN, int RELU_IN, int RELU_OUT>
__global__ __launch_bounds__(256)
void gemm_f2(const float* __restrict__ A, const float* __restrict__ W,
             float* __restrict__ C, int nrows, int K,
             long sA, long sW, long sC)
{
    const int BM = 128, BK = 8, TN = BN / 16;
    A += blockIdx.z * sA;
    W += blockIdx.z * sW;
    C += blockIdx.z * sC;

    __shared__ __align__(16) float As[BK][132];
    __shared__ __align__(16) float Ws[BK][BN];

    int tid = threadIdx.x;
    int tx = tid & 15;
    int ty = tid >> 4;
    int row0 = blockIdx.x * BM;

    int arow = tid >> 1;
    int akq = (tid & 1) * 4;
    int wk, wn4;
    if (BN == 128) { wk = tid >> 5; wn4 = (tid & 31) * 4; }
    else           { wk = tid >> 4; wn4 = (tid & 15) * 4; }

    unsigned long long acc2[4][TN];
#pragma unroll
    for (int i = 0; i < 4; i++)
#pragma unroll
        for (int j = 0; j < TN; j++) acc2[i][j] = 0ull;

    for (int k0 = 0; k0 < K; k0 += BK) {
        {
            int row = row0 + arow;
            float4 v = make_float4(0.f, 0.f, 0.f, 0.f);
            if (row < nrows)
                v = *(const float4*)(A + (long)row * K + k0 + akq);
            if (RELU_IN) {
                v.x = fmaxf(v.x, 0.f); v.y = fmaxf(v.y, 0.f);
                v.z = fmaxf(v.z, 0.f); v.w = fmaxf(v.w, 0.f);
            }
            As[akq + 0][arow] = v.x;
            As[akq + 1][arow] = v.y;
            As[akq + 2][arow] = v.z;
            As[akq + 3][arow] = v.w;
        }
        if (BN == 128 || tid < 128) {
            float4 v = *(const float4*)(W + (long)(k0 + wk) * BN + wn4);
            *(float4*)&Ws[wk][wn4] = v;
        }
        __syncthreads();

#pragma unroll
        for (int k = 0; k < BK; k++) {
            unsigned long long rav[4], rbv[TN];
#pragma unroll
            for (int i = 0; i < 4; i++) {
                float2 t = *(const float2*)&As[k][ty * 2 + i * 32];
                asm("mov.b64 %0, {%1, %2};" : "=l"(rav[i]) : "f"(t.x), "f"(t.y));
            }
#pragma unroll
            for (int j = 0; j < TN; j++) {
                float b = Ws[k][tx + j * 16];
                asm("mov.b64 %0, {%1, %1};" : "=l"(rbv[j]) : "f"(b));
            }
#pragma unroll
            for (int i = 0; i < 4; i++)
#pragma unroll
                for (int j = 0; j < TN; j++)
                    asm("fma.rn.f32x2 %0, %1, %2, %0;"
                        : "+l"(acc2[i][j]) : "l"(rav[i]), "l"(rbv[j]));
        }
        __syncthreads();
    }

#pragma unroll
    for (int i = 0; i < 4; i++) {
        int r0 = row0 + ty * 2 + i * 32;
#pragma unroll
        for (int j = 0; j < TN; j++) {
            float v0, v1;
            asm("mov.b64 {%0, %1}, %2;" : "=f"(v0), "=f"(v1) : "l"(acc2[i][j]));
            if (RELU_OUT) { v0 = fmaxf(v0, 0.f); v1 = fmaxf(v1, 0.f); }
            int col = tx + j * 16;
            if (r0 < nrows)     C[(long)r0 * BN + col] = v0;
            if (r0 + 1 < nrows) C[(long)(r0 + 1) * BN + col] = v1;
        }
    }
}

// ----------------------------------------------------------------------------
// Small register-tiled GEMM (heads / fc1): C = relu(A @ W + bias), BN=128.
// ----------------------------------------------------------------------------
__global__ void gemm_small(const float* __restrict__ A,
                           const float* __restrict__ W,
                           const float* __restrict__ bias,
                           float* __restrict__ C,
                           int nrows, int K, int ldA, int ldC,
                           long sA, long sW, long sC, long sB)
{
    const int BM = 64, BK = 16, TM = 4, BN = 128, TN = 8;
    A += blockIdx.z * sA;
    W += blockIdx.z * sW;
    C += blockIdx.z * sC;
    if (bias) bias += blockIdx.z * sB;

    __shared__ float As[BK][BM + 1];
    __shared__ float Ws[BK][BN];

    int tid = threadIdx.x;
    int tx = tid & 15;
    int ty = tid >> 4;
    int row0 = blockIdx.x * BM;

    float acc[TM][TN];
#pragma unroll
    for (int i = 0; i < TM; i++)
#pragma unroll
        for (int j = 0; j < TN; j++) acc[i][j] = 0.0f;

    for (int k0 = 0; k0 < K; k0 += BK) {
#pragma unroll
        for (int i = 0; i < (BM * BK) / 256; i++) {
            int t = tid + i * 256;
            int m = t >> 4;
            int k = t & 15;
            int row = row0 + m;
            As[k][m] = (row < nrows) ? A[(long)row * ldA + k0 + k] : 0.0f;
        }
#pragma unroll
        for (int i = 0; i < (BN * BK) / 256; i++) {
            int t = tid + i * 256;
            int n = t & 127;
            int k = t >> 7;
            Ws[k][n] = W[(long)(k0 + k) * BN + n];
        }
        __syncthreads();

#pragma unroll
        for (int k = 0; k < BK; k++) {
            float ra[TM], rb[TN];
#pragma unroll
            for (int i = 0; i < TM; i++) ra[i] = As[k][ty + i * 16];
#pragma unroll
            for (int j = 0; j < TN; j++) rb[j] = Ws[k][tx + j * 16];
#pragma unroll
            for (int i = 0; i < TM; i++)
#pragma unroll
                for (int j = 0; j < TN; j++)
                    acc[i][j] = fmaf(ra[i], rb[j], acc[i][j]);
        }
        __syncthreads();
    }

#pragma unroll
    for (int i = 0; i < TM; i++) {
        int row = row0 + ty + i * 16;
        if (row < nrows) {
#pragma unroll
            for (int j = 0; j < TN; j++) {
                int col = tx + j * 16;
                float v = acc[i][j];
                if (bias) v += bias[col];
                v = fmaxf(v, 0.0f);
                C[(long)row * ldC + col] = v;
            }
        }
    }
}

// ----------------------------------------------------------------------------
// Final fc2: out[row] = dot(hg2[row,:], W[:,0]) + b[0]
// ----------------------------------------------------------------------------
__global__ void fc2_kernel(const float* __restrict__ A,
                           const float* __restrict__ W,
                           const float* __restrict__ b,
                           float* __restrict__ out)
{
    int row = blockIdx.x;
    float v = A[row * DIM + threadIdx.x] * W[threadIdx.x];
#pragma unroll
    for (int o = 16; o > 0; o >>= 1) v += __shfl_down_sync(0xffffffffu, v, o);
    __shared__ float s[4];
    if ((threadIdx.x & 31) == 0) s[threadIdx.x >> 5] = v;
    __syncthreads();
    if (threadIdx.x == 0) out[row] = s[0] + s[1] + s[2] + s[3] + b[0];
}

// ----------------------------------------------------------------------------
// Host-side orchestration
// ----------------------------------------------------------------------------
static void run_branch(const float* x, const int* ei, const int* batchids,
                       const float* W0, const float* W1, const float* W2,
                       const float* fcW, const float* fcb,
                       int N, int E, float* hg_base,
                       float* p_ax, float* p_bufA, float* p_bufB, float* p_bufC,
                       float* p_rep,
                       int* p_cnt, int* p_rowptr, int* p_pos, int* p_ssrc)
{
    const int* src = ei;
    const int* dst = ei + E;
    unsigned gb = (unsigned)((N + 127) / 128);
    unsigned eb = (unsigned)((E + 255) / 256);

    // Build CSR (edges sorted by dst) for gather-side aggregation.
    cudaMemsetAsync(p_cnt, 0, (size_t)N * sizeof(int));
    hist_kernel<<<eb, 256>>>(dst, p_cnt, E);
    scan_kernel<<<1, 1024>>>(p_cnt, p_rowptr, p_pos, N, E);
    permute_kernel<<<eb, 256>>>(src, dst, p_pos, p_ssrc, E);

    // Layer 0 aggregation: ax = agg(x), shared across ensembles (64-wide).
    {
        long total = (long)N * 16;
        gather_csr_kernel<4, 1><<<(unsigned)((total + 255) / 256), 256>>>(
            x, p_ax, p_rowptr, p_ssrc, N, 0, 0);
    }

    // h0[e] = relu(ax @ W0[e])   (z-batched, A shared: sA=0)
    gemm_f2<128, 0, 1><<<dim3(gb, 1, ENS), 256>>>(
        p_ax, W0, p_bufA, N, FEAT, 0, (long)FEAT * DIM, SLOT);

    // g1[e] = h0[e] @ W1[e]
    gemm_f2<128, 0, 0><<<dim3(gb, 1, ENS), 256>>>(
        p_bufA, W1, p_bufB, N, DIM, SLOT, (long)DIM * DIM, SLOT);

    // a1[e] = agg(g1[e])   (128-wide, ensemble-fused gather)
    {
        long total = (long)N * 32;
        gather_csr_kernel<5, ENS><<<(unsigned)((total + 255) / 256), 256>>>(
            p_bufB, p_bufC, p_rowptr, p_ssrc, N, SLOT, SLOT);
    }

    // g2[e] = relu(a1[e]) @ W2[e]   (64-wide output)
    gemm_f2<64, 1, 0><<<dim3(gb, 1, ENS), 256>>>(
        p_bufC, W2, p_bufA, N, DIM, SLOT, (long)DIM * HALF, SLOT);

    // a2[e] = agg(g2[e])   (64-wide, ensemble-fused gather)
    {
        long total = (long)N * 16;
        gather_csr_kernel<4, ENS><<<(unsigned)((total + 255) / 256), 256>>>(
            p_bufA, p_bufB, p_rowptr, p_ssrc, N, SLOT, SLOT);
    }

    // Pool: rep[e] = segment_sum(relu(a2[e]), batchids)
    cudaMemsetAsync(p_rep, 0, (size_t)ENS * BATCH * HALF * sizeof(float));
    {
        long total = (long)N * 16;
        pool_vec_kernel<<<(unsigned)((total + 255) / 256), 256>>>(
            p_bufB, batchids, p_rep, N, SLOT, (long)BATCH * HALF);
    }

    // Heads: hg[:, off + e*128 ...] = relu(rep[e] @ fcW[e] + fcb[e])
    {
        dim3 g((BATCH + 63) / 64, 1, ENS);
        gemm_small<<<g, 256>>>(p_rep, fcW, fcb, hg_base, BATCH, HALF, HALF,
                               2 * ENS * DIM,
                               (long)BATCH * HALF, (long)HALF * DIM, DIM, DIM);
    }
}

extern "C" void kernel_launch(void* const* d_in, const int* in_sizes, int n_in,
                              void* d_out, int out_size)
{
    // Resolve input ordering at runtime (dict order vs signature order).
    int i_chr_x, i_slv_x, i_chr_ei, i_slv_ei, i_chr_b, i_slv_b;
    int i_cW0, i_cW1, i_cW2, i_sW0, i_sW1, i_sW2;
    int i_cfcW, i_cfcB, i_sfcW, i_sfcB, i_fc1W, i_fc1B, i_fc2W, i_fc2B;
    if (in_sizes[2] == 2 * E_CHR) {
        i_chr_x = 0;  i_slv_x = 1;  i_chr_ei = 2; i_slv_ei = 3;
        i_chr_b = 4;  i_slv_b = 5;
        i_cW0 = 6;  i_cW1 = 7;  i_cW2 = 8;
        i_sW0 = 9;  i_sW1 = 10; i_sW2 = 11;
        i_cfcW = 12; i_cfcB = 13; i_sfcW = 14; i_sfcB = 15;
        i_fc1W = 16; i_fc1B = 17; i_fc2W = 18; i_fc2B = 19;
    } else {
        i_chr_x = 0;  i_slv_x = 1;
        i_cW0 = 2;  i_cW1 = 3;  i_cW2 = 4;
        i_sW0 = 5;  i_sW1 = 6;  i_sW2 = 7;
        i_cfcW = 8;  i_cfcB = 9;  i_sfcW = 10; i_sfcB = 11;
        i_fc1W = 12; i_fc1B = 13; i_fc2W = 14; i_fc2B = 15;
        i_chr_ei = 16; i_slv_ei = 17; i_chr_b = 18; i_slv_b = 19;
    }

    const float* chr_x = (const float*)d_in[i_chr_x];
    const float* slv_x = (const float*)d_in[i_slv_x];
    const int* chr_ei = (const int*)d_in[i_chr_ei];
    const int* slv_ei = (const int*)d_in[i_slv_ei];
    const int* chr_bi = (const int*)d_in[i_chr_b];
    const int* slv_bi = (const int*)d_in[i_slv_b];
    const float* cW0 = (const float*)d_in[i_cW0];
    const float* cW1 = (const float*)d_in[i_cW1];
    const float* cW2 = (const float*)d_in[i_cW2];
    const float* sW0 = (const float*)d_in[i_sW0];
    const float* sW1 = (const float*)d_in[i_sW1];
    const float* sW2 = (const float*)d_in[i_sW2];
    const float* cfcW = (const float*)d_in[i_cfcW];
    const float* cfcB = (const float*)d_in[i_cfcB];
    const float* sfcW = (const float*)d_in[i_sfcW];
    const float* sfcB = (const float*)d_in[i_sfcB];
    const float* fc1W = (const float*)d_in[i_fc1W];
    const float* fc1B = (const float*)d_in[i_fc1B];
    const float* fc2W = (const float*)d_in[i_fc2W];
    const float* fc2B = (const float*)d_in[i_fc2B];

    float *p_ax, *p_bufA, *p_bufB, *p_bufC, *p_rep, *p_hg, *p_hg2;
    int *p_cnt, *p_rowptr, *p_pos, *p_ssrc;
    cudaGetSymbolAddress((void**)&p_ax,     g_ax);
    cudaGetSymbolAddress((void**)&p_bufA,   g_bufA);
    cudaGetSymbolAddress((void**)&p_bufB,   g_bufB);
    cudaGetSymbolAddress((void**)&p_bufC,   g_bufC);
    cudaGetSymbolAddress((void**)&p_rep,    g_rep);
    cudaGetSymbolAddress((void**)&p_hg,     g_hg);
    cudaGetSymbolAddress((void**)&p_hg2,    g_hg2);
    cudaGetSymbolAddress((void**)&p_cnt,    g_cnt);
    cudaGetSymbolAddress((void**)&p_rowptr, g_rowptr);
    cudaGetSymbolAddress((void**)&p_pos,    g_pos);
    cudaGetSymbolAddress((void**)&p_ssrc,   g_ssrc);

    // chr branch -> hg columns [0, 384)
    run_branch(chr_x, chr_ei, chr_bi, cW0, cW1, cW2, cfcW, cfcB,
               N_CHR, E_CHR, p_hg, p_ax, p_bufA, p_bufB, p_bufC, p_rep,
               p_cnt, p_rowptr, p_pos, p_ssrc);
    // slv branch -> hg columns [384, 768)  (reuses CSR scratch after chr)
    run_branch(slv_x, slv_ei, slv_bi, sW0, sW1, sW2, sfcW, sfcB,
               N_SLV, E_SLV, p_hg + ENS * DIM, p_ax, p_bufA, p_bufB, p_bufC, p_rep,
               p_cnt, p_rowptr, p_pos, p_ssrc);

    // fc1: hg2 = relu(hg @ fc1W + fc1B)   [256,768]@[768,128]
    {
        dim3 g((BATCH + 63) / 64, 1, 1);
        gemm_small<<<g, 256>>>(p_hg, fc1W, fc1B, p_hg2, BATCH, 2 * ENS * DIM,
                               2 * ENS * DIM, DIM, 0, 0, 0, 0);
    }

    // fc2: out = hg2 @ fc2W + fc2B   [256,128]@[128,1]
    fc2_kernel<<<BATCH, DIM>>>(p_hg2, fc2W, fc2B, (float*)d_out);
}